// round 1
// baseline (speedup 1.0000x reference)
#include <cuda_runtime.h>

// ---------------------------------------------------------------------------
// CompressiveMemory: out = (phi(Q) @ M_h) / max(phi(Q)·z_h, eps)
//                    M_new = M + phiK_b^T @ V_b   (batch-mean inputs)
//                    z_new = z + sum_t phiK_b
// phi(x) = elu(x)+1 = x>0 ? x+1 : exp(x)
// Shapes: Q,K,V (2,32,4096,128) f32; M (32,128,128); z (32,128)
// Output layout: [out (2*32*4096*128)][M_new (32*128*128)][z_new (32*128)]
// ---------------------------------------------------------------------------

#define B_SZ 2
#define H_SZ 32
#define T_SZ 4096
#define D_SZ 128
#define NCHUNK 8                 // t-chunks for the update reduction
#define CHUNK_T (T_SZ / NCHUNK)  // 512

#define OUT_ELEMS ((size_t)B_SZ * H_SZ * T_SZ * D_SZ)   // 33554432
#define MNEW_ELEMS (H_SZ * D_SZ * D_SZ)                  // 524288
#define ZNEW_ELEMS (H_SZ * D_SZ)                         // 4096

// Fixed-order reduction scratch (no cudaMalloc allowed)
__device__ float g_partM[H_SZ * NCHUNK * D_SZ * D_SZ];   // 16 MB
__device__ float g_partZ[H_SZ * NCHUNK * D_SZ];

__device__ __forceinline__ float phi(float x) {
    return x > 0.0f ? x + 1.0f : __expf(x);
}

// ---- packed f32x2 helpers (2x FFMA throughput on sm_103a) ----
__device__ __forceinline__ unsigned long long pack2(float lo, float hi) {
    unsigned long long r;
    asm("mov.b64 %0, {%1, %2};" : "=l"(r) : "f"(lo), "f"(hi));
    return r;
}
__device__ __forceinline__ void fma2(unsigned long long& d,
                                     unsigned long long a,
                                     unsigned long long b) {
    asm("fma.rn.f32x2 %0, %1, %2, %3;" : "=l"(d) : "l"(a), "l"(b), "l"(d));
}
__device__ __forceinline__ unsigned long long mul2(unsigned long long a,
                                                   unsigned long long b) {
    unsigned long long d;
    asm("mul.rn.f32x2 %0, %1, %2;" : "=l"(d) : "l"(a), "l"(b));
    return d;
}

// ---------------------------------------------------------------------------
// Kernel 1: retrieve.  grid (T/128, B*H), block 256.
// Per-thread microtile: 4 t-rows x 16 e-cols, f32x2 accumulators.
// smem: M_h (128x128, 64KB) + transposed phi(Q) k-tile [16][132] + z (128)
// ---------------------------------------------------------------------------
#define QST_LD 132
#define SMEM_A_BYTES ((16384 + 16 * QST_LD + 128) * 4)

__global__ void __launch_bounds__(256, 2)
retrieve_kernel(const float* __restrict__ Q, const float* __restrict__ M,
                const float* __restrict__ z, float* __restrict__ out)
{
    extern __shared__ float sm[];
    float* Ms  = sm;                   // [128][128]
    float* QsT = sm + 16384;           // [16][QST_LD]  (k-major, row = t)
    float* zs  = QsT + 16 * QST_LD;    // [128]

    const int tid = threadIdx.x;
    const int bh  = blockIdx.y;        // b*32 + h
    const int h   = bh & 31;
    const int t0  = blockIdx.x * 128;
    const int tx  = tid & 7;           // 0..7  -> e cols
    const int ty  = tid >> 3;          // 0..31 -> t rows
    const int tr  = ty * 4;
    const int ec  = tx * 16;

    const float* Qb = Q + ((size_t)bh * T_SZ + t0) * D_SZ;
    const float* Mb = M + (size_t)h * 16384;

    // stage M_h and z_h
    {
        const float4* src = (const float4*)Mb;
        float4* dst = (float4*)Ms;
        #pragma unroll
        for (int i = 0; i < 16; ++i) dst[tid + i * 256] = src[tid + i * 256];
        if (tid < 128) zs[tid] = z[h * 128 + tid];
    }

    unsigned long long acc[4][8];
    #pragma unroll
    for (int i = 0; i < 4; ++i)
        #pragma unroll
        for (int j = 0; j < 8; ++j) acc[i][j] = 0ULL;
    float nacc[4] = {0.f, 0.f, 0.f, 0.f};

    for (int kt = 0; kt < 8; ++kt) {
        __syncthreads();   // protect previous tile (also covers M/z staging)
        // stage transposed phi(Q) tile: QsT[kk][row]
        #pragma unroll
        for (int it = 0; it < 2; ++it) {
            int idx = tid + it * 256;        // float4 index over 128x16 tile
            int kk4 = idx & 3;
            int row = idx >> 2;
            float4 q = *(const float4*)(Qb + (size_t)row * D_SZ + kt * 16 + kk4 * 4);
            QsT[(kk4 * 4 + 0) * QST_LD + row] = phi(q.x);
            QsT[(kk4 * 4 + 1) * QST_LD + row] = phi(q.y);
            QsT[(kk4 * 4 + 2) * QST_LD + row] = phi(q.z);
            QsT[(kk4 * 4 + 3) * QST_LD + row] = phi(q.w);
        }
        __syncthreads();

        #pragma unroll
        for (int kk = 0; kk < 16; ++kk) {
            const int k = kt * 16 + kk;
            float4 av = *(const float4*)&QsT[kk * QST_LD + tr];
            float zk = zs[k];
            nacc[0] += av.x * zk;
            nacc[1] += av.y * zk;
            nacc[2] += av.z * zk;
            nacc[3] += av.w * zk;
            unsigned long long ad[4];
            ad[0] = pack2(av.x, av.x);
            ad[1] = pack2(av.y, av.y);
            ad[2] = pack2(av.z, av.z);
            ad[3] = pack2(av.w, av.w);
            const ulonglong2* bp = (const ulonglong2*)&Ms[k * 128 + ec];
            ulonglong2 b0 = bp[0], b1 = bp[1], b2 = bp[2], b3 = bp[3];
            unsigned long long bb[8] = {b0.x, b0.y, b1.x, b1.y,
                                        b2.x, b2.y, b3.x, b3.y};
            #pragma unroll
            for (int i = 0; i < 4; ++i)
                #pragma unroll
                for (int jp = 0; jp < 8; ++jp)
                    fma2(acc[i][jp], ad[i], bb[jp]);
        }
    }

    float* ob = out + ((size_t)bh * T_SZ + t0) * D_SZ;
    #pragma unroll
    for (int i = 0; i < 4; ++i) {
        float inv = 1.0f / fmaxf(nacc[i], 1e-6f);
        unsigned long long invd = pack2(inv, inv);
        ulonglong2* orow = (ulonglong2*)(ob + (size_t)(tr + i) * D_SZ + ec);
        #pragma unroll
        for (int q4 = 0; q4 < 4; ++q4) {
            ulonglong2 v;
            v.x = mul2(acc[i][2 * q4 + 0], invd);
            v.y = mul2(acc[i][2 * q4 + 1], invd);
            orow[q4] = v;
        }
    }
}

// ---------------------------------------------------------------------------
// Kernel 2: update partials. grid (NCHUNK, H), block 256.
// C[d][e] += sum_t phiK_b[t][d] * V_b[t][e] over a 512-t chunk (k-tiled by 16)
// ---------------------------------------------------------------------------
#define AB_LD 132

__global__ void __launch_bounds__(256, 2)
update_kernel(const float* __restrict__ K, const float* __restrict__ V)
{
    __shared__ float As[16 * AB_LD];   // phiK_b tile [t=16][d=128]
    __shared__ float Bs[16 * AB_LD];   // V_b   tile [t=16][e=128]

    const int tid = threadIdx.x;
    const int c = blockIdx.x;          // 0..7 t-chunk
    const int h = blockIdx.y;          // 0..31
    const int tx = tid & 7;
    const int ty = tid >> 3;
    const int dr = ty * 4;
    const int ec = tx * 16;

    const float* K0 = K + (size_t)h * T_SZ * D_SZ;
    const float* K1 = K + (size_t)(H_SZ + h) * T_SZ * D_SZ;
    const float* V0 = V + (size_t)h * T_SZ * D_SZ;
    const float* V1 = V + (size_t)(H_SZ + h) * T_SZ * D_SZ;
    const int t0 = c * CHUNK_T;

    unsigned long long acc[4][8];
    #pragma unroll
    for (int i = 0; i < 4; ++i)
        #pragma unroll
        for (int j = 0; j < 8; ++j) acc[i][j] = 0ULL;
    float zacc[4] = {0.f, 0.f, 0.f, 0.f};

    for (int kt = 0; kt < CHUNK_T / 16; ++kt) {
        const int tb = t0 + kt * 16;
        __syncthreads();
        // stage tiles (row-major t x d, coalesced float4)
        #pragma unroll
        for (int it = 0; it < 2; ++it) {
            int idx = tid + it * 256;  // float4 index over 16x128 tile
            int d4 = idx & 31;
            int trow = idx >> 5;
            size_t g = (size_t)(tb + trow) * D_SZ + d4 * 4;
            float4 k0 = *(const float4*)(K0 + g);
            float4 k1 = *(const float4*)(K1 + g);
            float4 a;
            a.x = 0.5f * (phi(k0.x) + phi(k1.x));
            a.y = 0.5f * (phi(k0.y) + phi(k1.y));
            a.z = 0.5f * (phi(k0.z) + phi(k1.z));
            a.w = 0.5f * (phi(k0.w) + phi(k1.w));
            *(float4*)&As[trow * AB_LD + d4 * 4] = a;
            float4 v0 = *(const float4*)(V0 + g);
            float4 v1 = *(const float4*)(V1 + g);
            float4 b;
            b.x = 0.5f * (v0.x + v1.x);
            b.y = 0.5f * (v0.y + v1.y);
            b.z = 0.5f * (v0.z + v1.z);
            b.w = 0.5f * (v0.w + v1.w);
            *(float4*)&Bs[trow * AB_LD + d4 * 4] = b;
        }
        __syncthreads();

        #pragma unroll
        for (int kk = 0; kk < 16; ++kk) {
            float4 av = *(const float4*)&As[kk * AB_LD + dr];
            zacc[0] += av.x;
            zacc[1] += av.y;
            zacc[2] += av.z;
            zacc[3] += av.w;
            unsigned long long ad[4];
            ad[0] = pack2(av.x, av.x);
            ad[1] = pack2(av.y, av.y);
            ad[2] = pack2(av.z, av.z);
            ad[3] = pack2(av.w, av.w);
            const ulonglong2* bp = (const ulonglong2*)&Bs[kk * AB_LD + ec];
            ulonglong2 b0 = bp[0], b1 = bp[1], b2 = bp[2], b3 = bp[3];
            unsigned long long bb[8] = {b0.x, b0.y, b1.x, b1.y,
                                        b2.x, b2.y, b3.x, b3.y};
            #pragma unroll
            for (int i = 0; i < 4; ++i)
                #pragma unroll
                for (int jp = 0; jp < 8; ++jp)
                    fma2(acc[i][jp], ad[i], bb[jp]);
        }
    }

    float* pm = g_partM + ((size_t)(h * NCHUNK + c) << 14);
    #pragma unroll
    for (int i = 0; i < 4; ++i) {
        ulonglong2* prow = (ulonglong2*)(pm + (size_t)(dr + i) * D_SZ + ec);
        #pragma unroll
        for (int q4 = 0; q4 < 4; ++q4) {
            ulonglong2 v;
            v.x = acc[i][2 * q4 + 0];
            v.y = acc[i][2 * q4 + 1];
            prow[q4] = v;
        }
    }
    if (tx == 0) {
        #pragma unroll
        for (int i = 0; i < 4; ++i)
            g_partZ[(h * NCHUNK + c) * D_SZ + dr + i] = zacc[i];
    }
}

// ---------------------------------------------------------------------------
// Kernel 3: deterministic fixed-order reduction of partials + M/z add
// ---------------------------------------------------------------------------
__global__ void reduce_kernel(const float* __restrict__ M,
                              const float* __restrict__ z,
                              float* __restrict__ outM,
                              float* __restrict__ outZ)
{
    int idx = blockIdx.x * 256 + threadIdx.x;
    if (idx < MNEW_ELEMS) {
        int h = idx >> 14;
        int r = idx & 16383;
        float s = M[idx];
        #pragma unroll
        for (int cc = 0; cc < NCHUNK; ++cc)
            s += g_partM[((size_t)(h * NCHUNK + cc) << 14) + r];
        outM[idx] = s;
    } else {
        int j = idx - MNEW_ELEMS;
        if (j < ZNEW_ELEMS) {
            int h = j >> 7;
            int d = j & 127;
            float s = z[j];
            #pragma unroll
            for (int cc = 0; cc < NCHUNK; ++cc)
                s += g_partZ[(h * NCHUNK + cc) * D_SZ + d];
            outZ[j] = s;
        }
    }
}

// ---------------------------------------------------------------------------
extern "C" void kernel_launch(void* const* d_in, const int* in_sizes, int n_in,
                              void* d_out, int out_size)
{
    const float* Q = (const float*)d_in[0];
    const float* K = (const float*)d_in[1];
    const float* V = (const float*)d_in[2];
    const float* M = (const float*)d_in[3];
    const float* z = (const float*)d_in[4];

    float* out  = (float*)d_out;
    float* outM = out + OUT_ELEMS;
    float* outZ = outM + MNEW_ELEMS;

    cudaFuncSetAttribute(retrieve_kernel,
                         cudaFuncAttributeMaxDynamicSharedMemorySize,
                         SMEM_A_BYTES);

    retrieve_kernel<<<dim3(T_SZ / 128, B_SZ * H_SZ), 256, SMEM_A_BYTES>>>(Q, M, z, out);
    update_kernel<<<dim3(NCHUNK, H_SZ), 256>>>(K, V);
    int red_threads = MNEW_ELEMS + ZNEW_ELEMS;
    reduce_kernel<<<(red_threads + 255) / 256, 256>>>(M, z, outM, outZ);
}

// round 4
// speedup vs baseline: 3.9182x; 3.9182x over previous
#include <cuda_runtime.h>
#include <cuda_bf16.h>
#include <cstdint>

// ---------------------------------------------------------------------------
// CompressiveMemory via fallback HMMA (mma.sync bf16) — tcgen05 rejected by
// the harness toolchain (PTX target compute_103 without 'a').
// out   = (phi(Q) @ M_h) / max(phi(Q)·z_h, eps)
// M_new = M + phiK_b^T @ V_b ;  z_new = z + sum_t phiK_b
// Shapes: Q,K,V (2,32,4096,128) f32; M (32,128,128); z (32,128)
// ---------------------------------------------------------------------------

#define B_SZ 2
#define H_SZ 32
#define T_SZ 4096
#define D_SZ 128
#define NCHUNK 8
#define CHUNK_T (T_SZ / NCHUNK)

#define OUT_ELEMS ((size_t)B_SZ * H_SZ * T_SZ * D_SZ)
#define MNEW_ELEMS (H_SZ * D_SZ * D_SZ)
#define ZNEW_ELEMS (H_SZ * D_SZ)

// B image: rows n=0..135 (0..127 = M^T, 128 = z, 129..135 = 0), 256B/row
// (128 bf16 k), XOR swizzle chunk^(n&7). hi split at +0, lo at +34816.
#define B_PART 34816
#define B_IMG 69632

__device__ __align__(16) unsigned char g_Bimg[H_SZ * B_IMG];
__device__ __align__(16) float g_partM[H_SZ * NCHUNK * D_SZ * D_SZ];
__device__ __align__(16) float g_partZ[H_SZ * NCHUNK * D_SZ];

__device__ __forceinline__ float phi(float x) {
    return x > 0.0f ? x + 1.0f : __expf(x);
}

// pack (lo,hi) floats into bf16x2 word (lo in low half)
__device__ __forceinline__ uint32_t pkbf2(float lo, float hi) {
    uint32_t d;
    asm("cvt.rn.bf16x2.f32 %0, %2, %1;" : "=r"(d) : "f"(lo), "f"(hi));
    return d;
}
__device__ __forceinline__ float ubf_lo(uint32_t w) { return __uint_as_float(w << 16); }
__device__ __forceinline__ float ubf_hi(uint32_t w) { return __uint_as_float(w & 0xFFFF0000u); }

__device__ __forceinline__ uint32_t smem_u32(const void* p) {
    uint32_t a;
    asm("{ .reg .u64 t; cvta.to.shared.u64 t, %1; cvt.u32.u64 %0, t; }"
        : "=r"(a) : "l"(p));
    return a;
}

// ---- ldmatrix / mma / cp.async ----
__device__ __forceinline__ void ldm4(uint32_t* r, uint32_t a) {
    asm volatile("ldmatrix.sync.aligned.m8n8.x4.shared.b16 {%0,%1,%2,%3}, [%4];"
                 : "=r"(r[0]), "=r"(r[1]), "=r"(r[2]), "=r"(r[3]) : "r"(a));
}
__device__ __forceinline__ void ldm4t(uint32_t* r, uint32_t a) {
    asm volatile("ldmatrix.sync.aligned.m8n8.x4.trans.shared.b16 {%0,%1,%2,%3}, [%4];"
                 : "=r"(r[0]), "=r"(r[1]), "=r"(r[2]), "=r"(r[3]) : "r"(a));
}
__device__ __forceinline__ void ldm2(uint32_t* r, uint32_t a) {
    asm volatile("ldmatrix.sync.aligned.m8n8.x2.shared.b16 {%0,%1}, [%2];"
                 : "=r"(r[0]), "=r"(r[1]) : "r"(a));
}
__device__ __forceinline__ void mma16816(float* c, const uint32_t* a,
                                         const uint32_t* b) {
    asm volatile(
        "mma.sync.aligned.m16n8k16.row.col.f32.bf16.bf16.f32 "
        "{%0,%1,%2,%3}, {%4,%5,%6,%7}, {%8,%9}, {%0,%1,%2,%3};"
        : "+f"(c[0]), "+f"(c[1]), "+f"(c[2]), "+f"(c[3])
        : "r"(a[0]), "r"(a[1]), "r"(a[2]), "r"(a[3]), "r"(b[0]), "r"(b[1]));
}
__device__ __forceinline__ void cpa16(uint32_t s, const void* g) {
    asm volatile("cp.async.cg.shared.global [%0], [%1], 16;" :: "r"(s), "l"(g));
}
#define CP_COMMIT() asm volatile("cp.async.commit_group;" ::: "memory")
#define CP_WAIT0()  asm volatile("cp.async.wait_group 0;" ::: "memory")

// swizzled byte offset inside a [rows][128 bf16] tile (256B rows)
__device__ __forceinline__ uint32_t sw_off(int row, int kc4) {
    // kc4 = k/4 (0..31); returns offset of the 8B group k..k+3
    return (uint32_t)(row * 256 + ((((kc4 >> 1) ^ (row & 7)) << 4) | ((kc4 & 1) << 3)));
}

// ---------------------------------------------------------------------------
// prep: bake per-head B image (M^T + z row), hi/lo split, swizzled.
// one block per head; padded smem transpose.
// ---------------------------------------------------------------------------
#define PREP_SMEM (128 * 129 * 4)

__global__ void __launch_bounds__(256) prep_kernel(const float* __restrict__ M,
                                                   const float* __restrict__ z)
{
    extern __shared__ float ps[];
    const int h = blockIdx.x;
    const int tid = threadIdx.x;
    const float* Mh = M + (size_t)h * 16384;

    for (int i = tid; i < 4096; i += 256) {      // float4 over [k][n]
        int k = i >> 5, c4 = i & 31;
        float4 m = ((const float4*)Mh)[i];
        float* p = ps + k * 129 + c4 * 4;
        p[0] = m.x; p[1] = m.y; p[2] = m.z; p[3] = m.w;
    }
    __syncthreads();

    unsigned char* img = g_Bimg + (size_t)h * B_IMG;
    for (int i = tid; i < 4096; i += 256) {      // (n, kc4)
        int n = i >> 5, kc = i & 31;
        float v0 = ps[(kc * 4 + 0) * 129 + n];
        float v1 = ps[(kc * 4 + 1) * 129 + n];
        float v2 = ps[(kc * 4 + 2) * 129 + n];
        float v3 = ps[(kc * 4 + 3) * 129 + n];
        uint32_t h01 = pkbf2(v0, v1), h23 = pkbf2(v2, v3);
        uint32_t l01 = pkbf2(v0 - ubf_lo(h01), v1 - ubf_hi(h01));
        uint32_t l23 = pkbf2(v2 - ubf_lo(h23), v3 - ubf_hi(h23));
        uint32_t off = sw_off(n, kc);
        *(uint2*)(img + off) = make_uint2(h01, h23);
        *(uint2*)(img + B_PART + off) = make_uint2(l01, l23);
    }
    if (tid < 32) {                              // z row at n=128
        int kc = tid;
        float4 zv = *(const float4*)(z + h * 128 + kc * 4);
        uint32_t h01 = pkbf2(zv.x, zv.y), h23 = pkbf2(zv.z, zv.w);
        uint32_t l01 = pkbf2(zv.x - ubf_lo(h01), zv.y - ubf_hi(h01));
        uint32_t l23 = pkbf2(zv.z - ubf_lo(h23), zv.w - ubf_hi(h23));
        uint32_t off = sw_off(128, kc);
        *(uint2*)(img + off) = make_uint2(h01, h23);
        *(uint2*)(img + B_PART + off) = make_uint2(l01, l23);
    }
    if (tid < 224) {                             // zero rows 129..135
        *(uint64_t*)(img + 129 * 256 + tid * 8) = 0ULL;
        *(uint64_t*)(img + B_PART + 129 * 256 + tid * 8) = 0ULL;
    }
}

// ---------------------------------------------------------------------------
// retrieve: grid (4, 64), 256 thr. 8 t-tiles of 128 per block.
// warp (wr = wid&1 -> 64 m-rows, wc = wid>>1 -> 32 n-cols).
// ---------------------------------------------------------------------------
#define RT_SM_B 0
#define RT_SM_AH 69632
#define RT_SM_AL 102400
#define RT_SM_STG 135168
#define RT_SM_NORM 200704
#define RT_SMEM 202752
#define RT_TILES 8

__global__ void __launch_bounds__(256)
retrieve_hmma(const float* __restrict__ Q, float* __restrict__ out)
{
    extern __shared__ unsigned char sm[];
    const uint32_t sb = smem_u32(sm);
    const int tid = threadIdx.x;
    const int l = tid & 31;
    const int wid = tid >> 5;
    const int wr = wid & 1;
    const int wc = wid >> 1;
    const int bh = blockIdx.y;
    const int h = bh & 31;
    const int tbase = blockIdx.x * (RT_TILES * 128);

    const float* Qt = Q + ((size_t)bh * T_SZ + tbase) * D_SZ;
    float* ob = out + ((size_t)bh * T_SZ + tbase) * D_SZ;

    // prologue: B image + stage tile 0
    {
        const unsigned char* bimg = g_Bimg + (size_t)h * B_IMG;
        for (int i = tid; i < B_IMG / 16; i += 256)
            cpa16(sb + RT_SM_B + i * 16, bimg + (size_t)i * 16);
        for (int i = tid; i < 4096; i += 256)
            cpa16(sb + RT_SM_STG + i * 16, (const char*)Qt + (size_t)i * 16);
        CP_COMMIT();
    }

    // per-lane invariants
    const int arowl = l & 15;                 // A row within m-frag
    const int ag = (l >> 4) & 1;              // A k-chunk select
    const int a7 = arowl & 7;
    const int browl = (l & 7) + ((l >> 4) << 3);
    const int bg = (l >> 3) & 1;
    const int b7 = browl & 7;
    const int le = l & 15;
    const int zrow = 128 + (le & 7);
    const int zg = (le >> 3) & 1;
    const int z7 = zrow & 7;

    uint32_t aoffm[4], boffp[2];
    #pragma unroll
    for (int mi = 0; mi < 4; ++mi)
        aoffm[mi] = (uint32_t)((wr * 64 + mi * 16 + arowl) * 256);
    #pragma unroll
    for (int p = 0; p < 2; ++p)
        boffp[p] = (uint32_t)((wc * 32 + p * 16 + browl) * 256);
    const uint32_t zoff = (uint32_t)(zrow * 256);

    for (int tile = 0; tile < RT_TILES; ++tile) {
        CP_WAIT0();
        __syncthreads();

        // convert stage (fp32) -> AH/AL bf16 swizzled
        #pragma unroll
        for (int i = 0; i < 16; ++i) {
            int idx = tid + i * 256;
            int row = idx >> 5, c4 = idx & 31;
            float4 q = *(const float4*)(sm + RT_SM_STG + (size_t)idx * 16);
            float p0 = phi(q.x), p1 = phi(q.y), p2 = phi(q.z), p3 = phi(q.w);
            uint32_t h01 = pkbf2(p0, p1), h23 = pkbf2(p2, p3);
            uint32_t l01 = pkbf2(p0 - ubf_lo(h01), p1 - ubf_hi(h01));
            uint32_t l23 = pkbf2(p2 - ubf_lo(h23), p3 - ubf_hi(h23));
            uint32_t off = sw_off(row, c4);
            *(uint2*)(sm + RT_SM_AH + off) = make_uint2(h01, h23);
            *(uint2*)(sm + RT_SM_AL + off) = make_uint2(l01, l23);
        }
        __syncthreads();

        // prefetch next tile into stage
        if (tile + 1 < RT_TILES) {
            const char* nq = (const char*)(Qt + (size_t)(tile + 1) * 16384);
            for (int i = tid; i < 4096; i += 256)
                cpa16(sb + RT_SM_STG + i * 16, nq + (size_t)i * 16);
        }
        CP_COMMIT();

        float acc[4][4][4];
        float zac[4][4];
        #pragma unroll
        for (int mi = 0; mi < 4; ++mi) {
            #pragma unroll
            for (int nj = 0; nj < 4; ++nj)
                #pragma unroll
                for (int q = 0; q < 4; ++q) acc[mi][nj][q] = 0.f;
            #pragma unroll
            for (int q = 0; q < 4; ++q) zac[mi][q] = 0.f;
        }

        #pragma unroll
        for (int ks = 0; ks < 8; ++ks) {
            const int cb = ks * 2;
            const uint32_t ach = (uint32_t)((cb + ag) ^ a7) << 4;
            const uint32_t bch = (uint32_t)((cb + bg) ^ b7) << 4;

            uint32_t AhF[4][4], AlF[4][4];
            #pragma unroll
            for (int mi = 0; mi < 4; ++mi) {
                ldm4(AhF[mi], sb + RT_SM_AH + aoffm[mi] + ach);
                ldm4(AlF[mi], sb + RT_SM_AL + aoffm[mi] + ach);
            }
            uint32_t BhF[4][2], BlF[4][2];
            #pragma unroll
            for (int p = 0; p < 2; ++p) {
                uint32_t r[4];
                ldm4(r, sb + RT_SM_B + boffp[p] + bch);
                BhF[2 * p][0] = r[0]; BhF[2 * p][1] = r[1];
                BhF[2 * p + 1][0] = r[2]; BhF[2 * p + 1][1] = r[3];
                ldm4(r, sb + RT_SM_B + B_PART + boffp[p] + bch);
                BlF[2 * p][0] = r[0]; BlF[2 * p][1] = r[1];
                BlF[2 * p + 1][0] = r[2]; BlF[2 * p + 1][1] = r[3];
            }

            #pragma unroll
            for (int mi = 0; mi < 4; ++mi)
                #pragma unroll
                for (int nj = 0; nj < 4; ++nj)
                    mma16816(acc[mi][nj], AhF[mi], BhF[nj]);
            #pragma unroll
            for (int mi = 0; mi < 4; ++mi)
                #pragma unroll
                for (int nj = 0; nj < 4; ++nj)
                    mma16816(acc[mi][nj], AhF[mi], BlF[nj]);
            #pragma unroll
            for (int mi = 0; mi < 4; ++mi)
                #pragma unroll
                for (int nj = 0; nj < 4; ++nj)
                    mma16816(acc[mi][nj], AlF[mi], BhF[nj]);

            if ((ks & 3) == wc) {     // striped z work
                const uint32_t zch = (uint32_t)((cb + zg) ^ z7) << 4;
                uint32_t zh[2], zl2[2];
                ldm2(zh, sb + RT_SM_B + zoff + zch);
                ldm2(zl2, sb + RT_SM_B + B_PART + zoff + zch);
                #pragma unroll
                for (int mi = 0; mi < 4; ++mi) {
                    mma16816(zac[mi], AhF[mi], zh);
                    mma16816(zac[mi], AhF[mi], zl2);
                    mma16816(zac[mi], AlF[mi], zh);
                }
            }
        }

        // epilogue
        float* norms = (float*)(sm + RT_SM_NORM);   // [4][128]
        if ((l & 3) == 0) {
            #pragma unroll
            for (int mi = 0; mi < 4; ++mi) {
                int r = wr * 64 + mi * 16 + (l >> 2);
                norms[wc * 128 + r] = zac[mi][0];
                norms[wc * 128 + r + 8] = zac[mi][2];
            }
        }
        __syncthreads();

        #pragma unroll
        for (int mi = 0; mi < 4; ++mi) {
            int r = wr * 64 + mi * 16 + (l >> 2);
            float n1 = norms[r] + norms[128 + r] + norms[256 + r] + norms[384 + r];
            float n2 = norms[r + 8] + norms[128 + r + 8] + norms[256 + r + 8] +
                       norms[384 + r + 8];
            float i1 = 1.0f / fmaxf(n1, 1e-6f);
            float i2 = 1.0f / fmaxf(n2, 1e-6f);
            float* o1 = ob + (size_t)(tile * 128 + r) * 128 + wc * 32 + (l & 3) * 2;
            float* o2 = o1 + (size_t)8 * 128;
            #pragma unroll
            for (int nj = 0; nj < 4; ++nj) {
                *(float2*)(o1 + nj * 8) =
                    make_float2(acc[mi][nj][0] * i1, acc[mi][nj][1] * i1);
                *(float2*)(o2 + nj * 8) =
                    make_float2(acc[mi][nj][2] * i2, acc[mi][nj][3] * i2);
            }
        }
        __syncthreads();
    }
}

// ---------------------------------------------------------------------------
// update: grid (NCHUNK, 32), 256 thr. C[d][e] = sum_t phiKb[t][d] Vb[t][e]
// over a 512-t chunk; ldmatrix.trans on [t][d]/[t][e] tiles. Partials -> gmem.
// ---------------------------------------------------------------------------
#define UP_AH 0
#define UP_AL 16384
#define UP_BH 32768
#define UP_BL 49152
#define UP_STG 65536          // SK0 +0, SK1 +32768, SV0 +65536, SV1 +98304
#define UP_SMEM 196608

__global__ void __launch_bounds__(256)
update_hmma(const float* __restrict__ K, const float* __restrict__ V)
{
    extern __shared__ unsigned char sm[];
    const uint32_t sb = smem_u32(sm);
    const int tid = threadIdx.x;
    const int l = tid & 31;
    const int wid = tid >> 5;
    const int wr = wid & 1;
    const int wc = wid >> 1;
    const int c = blockIdx.x;
    const int h = blockIdx.y;

    const char* K0 = (const char*)(K + ((size_t)h * T_SZ + c * CHUNK_T) * D_SZ);
    const char* K1 = (const char*)(K + ((size_t)(H_SZ + h) * T_SZ + c * CHUNK_T) * D_SZ);
    const char* V0 = (const char*)(V + ((size_t)h * T_SZ + c * CHUNK_T) * D_SZ);
    const char* V1 = (const char*)(V + ((size_t)(H_SZ + h) * T_SZ + c * CHUNK_T) * D_SZ);

    // stage si = 64 t-rows of all four tensors
    {
        for (int i = tid; i < 2048; i += 256) {
            cpa16(sb + UP_STG + i * 16, K0 + (size_t)i * 16);
            cpa16(sb + UP_STG + 32768 + i * 16, K1 + (size_t)i * 16);
            cpa16(sb + UP_STG + 65536 + i * 16, V0 + (size_t)i * 16);
            cpa16(sb + UP_STG + 98304 + i * 16, V1 + (size_t)i * 16);
        }
        CP_COMMIT();
    }

    // lane invariants (trans addressing)
    const int atr = (l & 7) + ((l >> 4) << 3);     // A storage-row (t) offset
    const int aag = (l >> 3) & 1;                  // A chunk (+1 for m8-15)
    const int at7 = atr & 7;
    const int btr = (l & 7) + (((l >> 3) & 1) << 3);
    const int bbg = (l >> 4) & 1;
    const int bt7 = btr & 7;

    float acc[4][4][4];
    #pragma unroll
    for (int mi = 0; mi < 4; ++mi)
        #pragma unroll
        for (int nj = 0; nj < 4; ++nj)
            #pragma unroll
            for (int q = 0; q < 4; ++q) acc[mi][nj][q] = 0.f;
    float za0 = 0.f, za1 = 0.f, za2 = 0.f, za3 = 0.f;
    const int myc4 = tid & 31;

    for (int si = 0; si < 8; ++si) {
        CP_WAIT0();
        __syncthreads();

        // convert: phiKb -> A tiles (with z accumulation), Vb -> B tiles
        #pragma unroll
        for (int i = 0; i < 8; ++i) {
            int idx = tid + i * 256;
            int row = idx >> 5;
            float4 k0 = *(const float4*)(sm + UP_STG + (size_t)idx * 16);
            float4 k1 = *(const float4*)(sm + UP_STG + 32768 + (size_t)idx * 16);
            float a0 = 0.5f * (phi(k0.x) + phi(k1.x));
            float a1 = 0.5f * (phi(k0.y) + phi(k1.y));
            float a2 = 0.5f * (phi(k0.z) + phi(k1.z));
            float a3 = 0.5f * (phi(k0.w) + phi(k1.w));
            za0 += a0; za1 += a1; za2 += a2; za3 += a3;
            uint32_t h01 = pkbf2(a0, a1), h23 = pkbf2(a2, a3);
            uint32_t l01 = pkbf2(a0 - ubf_lo(h01), a1 - ubf_hi(h01));
            uint32_t l23 = pkbf2(a2 - ubf_lo(h23), a3 - ubf_hi(h23));
            uint32_t off = sw_off(row, myc4);
            *(uint2*)(sm + UP_AH + off) = make_uint2(h01, h23);
            *(uint2*)(sm + UP_AL + off) = make_uint2(l01, l23);

            float4 v0 = *(const float4*)(sm + UP_STG + 65536 + (size_t)idx * 16);
            float4 v1 = *(const float4*)(sm + UP_STG + 98304 + (size_t)idx * 16);
            float b0 = 0.5f * (v0.x + v1.x), b1 = 0.5f * (v0.y + v1.y);
            float b2 = 0.5f * (v0.z + v1.z), b3 = 0.5f * (v0.w + v1.w);
            uint32_t bh01 = pkbf2(b0, b1), bh23 = pkbf2(b2, b3);
            uint32_t bl01 = pkbf2(b0 - ubf_lo(bh01), b1 - ubf_hi(bh01));
            uint32_t bl23 = pkbf2(b2 - ubf_lo(bh23), b3 - ubf_hi(bh23));
            *(uint2*)(sm + UP_BH + off) = make_uint2(bh01, bh23);
            *(uint2*)(sm + UP_BL + off) = make_uint2(bl01, bl23);
        }
        __syncthreads();

        if (si + 1 < 8) {
            size_t go = (size_t)(si + 1) * 32768;
            for (int i = tid; i < 2048; i += 256) {
                cpa16(sb + UP_STG + i * 16, K0 + go + (size_t)i * 16);
                cpa16(sb + UP_STG + 32768 + i * 16, K1 + go + (size_t)i * 16);
                cpa16(sb + UP_STG + 65536 + i * 16, V0 + go + (size_t)i * 16);
                cpa16(sb + UP_STG + 98304 + i * 16, V1 + go + (size_t)i * 16);
            }
        }
        CP_COMMIT();

        #pragma unroll
        for (int ks = 0; ks < 4; ++ks) {
            const int k0t = ks * 16;
            uint32_t AhF[4][4], AlF[4][4];
            #pragma unroll
            for (int mi = 0; mi < 4; ++mi) {
                uint32_t ch = (uint32_t)(((wr * 8 + mi * 2 + aag) ^ at7) << 4);
                uint32_t addr = (uint32_t)((k0t + atr) * 256) + ch;
                ldm4t(AhF[mi], sb + UP_AH + addr);
                ldm4t(AlF[mi], sb + UP_AL + addr);
            }
            uint32_t BhF[4][2], BlF[4][2];
            #pragma unroll
            for (int p = 0; p < 2; ++p) {
                uint32_t ch = (uint32_t)(((wc * 4 + p * 2 + bbg) ^ bt7) << 4);
                uint32_t addr = (uint32_t)((k0t + btr) * 256) + ch;
                uint32_t r[4];
                ldm4t(r, sb + UP_BH + addr);
                BhF[2 * p][0] = r[0]; BhF[2 * p][1] = r[1];
                BhF[2 * p + 1][0] = r[2]; BhF[2 * p + 1][1] = r[3];
                ldm4t(r, sb + UP_BL + addr);
                BlF[2 * p][0] = r[0]; BlF[2 * p][1] = r[1];
                BlF[2 * p + 1][0] = r[2]; BlF[2 * p + 1][1] = r[3];
            }
            #pragma unroll
            for (int mi = 0; mi < 4; ++mi)
                #pragma unroll
                for (int nj = 0; nj < 4; ++nj)
                    mma16816(acc[mi][nj], AhF[mi], BhF[nj]);
            #pragma unroll
            for (int mi = 0; mi < 4; ++mi)
                #pragma unroll
                for (int nj = 0; nj < 4; ++nj)
                    mma16816(acc[mi][nj], AhF[mi], BlF[nj]);
            #pragma unroll
            for (int mi = 0; mi < 4; ++mi)
                #pragma unroll
                for (int nj = 0; nj < 4; ++nj)
                    mma16816(acc[mi][nj], AlF[mi], BhF[nj]);
        }
    }
    __syncthreads();

    // deterministic z reduction via smem (reuse stage region)
    float* zr = (float*)(sm + UP_STG);              // [8][128]
    *(float4*)(zr + (tid >> 5) * 128 + myc4 * 4) = make_float4(za0, za1, za2, za3);
    __syncthreads();
    if (tid < 128) {
        float s = 0.f;
        #pragma unroll
        for (int j = 0; j < 8; ++j) s += zr[j * 128 + tid];
        g_partZ[(h * NCHUNK + c) * 128 + tid] = s;
    }

    // write M partials
    float* pm = g_partM + ((size_t)(h * NCHUNK + c) << 14);
    #pragma unroll
    for (int mi = 0; mi < 4; ++mi) {
        int r = wr * 64 + mi * 16 + (l >> 2);
        #pragma unroll
        for (int nj = 0; nj < 4; ++nj) {
            int col = wc * 32 + nj * 8 + (l & 3) * 2;
            *(float2*)(pm + (size_t)r * 128 + col) =
                make_float2(acc[mi][nj][0], acc[mi][nj][1]);
            *(float2*)(pm + (size_t)(r + 8) * 128 + col) =
                make_float2(acc[mi][nj][2], acc[mi][nj][3]);
        }
    }
}

// ---------------------------------------------------------------------------
// fixed-order reduction of partials + M/z add
// ---------------------------------------------------------------------------
__global__ void reduce_kernel(const float* __restrict__ M,
                              const float* __restrict__ z,
                              float* __restrict__ outM,
                              float* __restrict__ outZ)
{
    int idx = blockIdx.x * 256 + threadIdx.x;
    if (idx < MNEW_ELEMS) {
        int h = idx >> 14;
        int r = idx & 16383;
        float s = M[idx];
        #pragma unroll
        for (int cc = 0; cc < NCHUNK; ++cc)
            s += g_partM[((size_t)(h * NCHUNK + cc) << 14) + r];
        outM[idx] = s;
    } else {
        int j = idx - MNEW_ELEMS;
        if (j < ZNEW_ELEMS) {
            int h = j >> 7;
            int d = j & 127;
            float s = z[j];
            #pragma unroll
            for (int cc = 0; cc < NCHUNK; ++cc)
                s += g_partZ[(h * NCHUNK + cc) * 128 + d];
            outZ[j] = s;
        }
    }
}

// ---------------------------------------------------------------------------
extern "C" void kernel_launch(void* const* d_in, const int* in_sizes, int n_in,
                              void* d_out, int out_size)
{
    const float* Q = (const float*)d_in[0];
    const float* K = (const float*)d_in[1];
    const float* V = (const float*)d_in[2];
    const float* M = (const float*)d_in[3];
    const float* z = (const float*)d_in[4];

    float* out  = (float*)d_out;
    float* outM = out + OUT_ELEMS;
    float* outZ = outM + MNEW_ELEMS;

    cudaFuncSetAttribute(prep_kernel,
                         cudaFuncAttributeMaxDynamicSharedMemorySize, PREP_SMEM);
    cudaFuncSetAttribute(retrieve_hmma,
                         cudaFuncAttributeMaxDynamicSharedMemorySize, RT_SMEM);
    cudaFuncSetAttribute(update_hmma,
                         cudaFuncAttributeMaxDynamicSharedMemorySize, UP_SMEM);

    prep_kernel<<<H_SZ, 256, PREP_SMEM>>>(M, z);
    retrieve_hmma<<<dim3(T_SZ / (RT_TILES * 128), B_SZ * H_SZ), 256, RT_SMEM>>>(Q, out);
    update_hmma<<<dim3(NCHUNK, H_SZ), 256, UP_SMEM>>>(K, V);
    int red_threads = MNEW_ELEMS + ZNEW_ELEMS;
    reduce_kernel<<<(red_threads + 255) / 256, 256>>>(M, z, outM, outZ);
}

// round 5
// speedup vs baseline: 4.6393x; 1.1841x over previous
#include <cuda_runtime.h>
#include <cuda_fp16.h>
#include <cstdint>

// ---------------------------------------------------------------------------
// CompressiveMemory via fallback HMMA (mma.sync f16, fp32 accum).
// 2-term split: A (phi(Q)/phi(K)) single fp16; B (M||z image, V) split hi+lo.
// out   = (phi(Q) @ M_h) / max(phi(Q)·z_h, eps)
// M_new = M + phiK_b^T @ V_b ;  z_new = z + sum_t phiK_b
// ---------------------------------------------------------------------------

#define B_SZ 2
#define H_SZ 32
#define T_SZ 4096
#define D_SZ 128
#define NCHUNK 8
#define CHUNK_T (T_SZ / NCHUNK)

#define OUT_ELEMS ((size_t)B_SZ * H_SZ * T_SZ * D_SZ)
#define MNEW_ELEMS (H_SZ * D_SZ * D_SZ)
#define ZNEW_ELEMS (H_SZ * D_SZ)

// B image: rows n=0..135 (0..127 = M^T, 128 = z, 129..135 = 0), 256B/row
// (128 f16 k), XOR swizzle chunk^(n&7). hi split at +0, lo at +34816.
#define B_PART 34816
#define B_IMG 69632

__device__ __align__(16) unsigned char g_Bimg[H_SZ * B_IMG];
__device__ __align__(16) float g_partM[H_SZ * NCHUNK * D_SZ * D_SZ];
__device__ __align__(16) float g_partZ[H_SZ * NCHUNK * D_SZ];

__device__ __forceinline__ float phi(float x) {
    return x > 0.0f ? x + 1.0f : __expf(x);
}

// pack (lo,hi) floats into f16x2 word (lo in low half)
__device__ __forceinline__ uint32_t pkh2(float lo, float hi) {
    uint32_t d;
    asm("cvt.rn.f16x2.f32 %0, %2, %1;" : "=r"(d) : "f"(lo), "f"(hi));
    return d;
}
__device__ __forceinline__ uint32_t smem_u32(const void* p) {
    uint32_t a;
    asm("{ .reg .u64 t; cvta.to.shared.u64 t, %1; cvt.u32.u64 %0, t; }"
        : "=r"(a) : "l"(p));
    return a;
}

// ---- ldmatrix / mma / cp.async ----
__device__ __forceinline__ void ldm4(uint32_t* r, uint32_t a) {
    asm volatile("ldmatrix.sync.aligned.m8n8.x4.shared.b16 {%0,%1,%2,%3}, [%4];"
                 : "=r"(r[0]), "=r"(r[1]), "=r"(r[2]), "=r"(r[3]) : "r"(a));
}
__device__ __forceinline__ void ldm4t(uint32_t* r, uint32_t a) {
    asm volatile("ldmatrix.sync.aligned.m8n8.x4.trans.shared.b16 {%0,%1,%2,%3}, [%4];"
                 : "=r"(r[0]), "=r"(r[1]), "=r"(r[2]), "=r"(r[3]) : "r"(a));
}
__device__ __forceinline__ void ldm2(uint32_t* r, uint32_t a) {
    asm volatile("ldmatrix.sync.aligned.m8n8.x2.shared.b16 {%0,%1}, [%2];"
                 : "=r"(r[0]), "=r"(r[1]) : "r"(a));
}
__device__ __forceinline__ void mma16816(float* c, const uint32_t* a,
                                         const uint32_t* b) {
    asm volatile(
        "mma.sync.aligned.m16n8k16.row.col.f32.f16.f16.f32 "
        "{%0,%1,%2,%3}, {%4,%5,%6,%7}, {%8,%9}, {%0,%1,%2,%3};"
        : "+f"(c[0]), "+f"(c[1]), "+f"(c[2]), "+f"(c[3])
        : "r"(a[0]), "r"(a[1]), "r"(a[2]), "r"(a[3]), "r"(b[0]), "r"(b[1]));
}
__device__ __forceinline__ void cpa16(uint32_t s, const void* g) {
    asm volatile("cp.async.cg.shared.global [%0], [%1], 16;" :: "r"(s), "l"(g));
}
#define CP_COMMIT() asm volatile("cp.async.commit_group;" ::: "memory")
#define CP_WAIT0()  asm volatile("cp.async.wait_group 0;" ::: "memory")

// swizzled byte offset inside a [rows][128 f16] tile (256B rows)
__device__ __forceinline__ uint32_t sw_off(int row, int kc4) {
    return (uint32_t)(row * 256 + ((((kc4 >> 1) ^ (row & 7)) << 4) | ((kc4 & 1) << 3)));
}

// ---------------------------------------------------------------------------
// prep: bake per-head B image (M^T + z row), f16 hi/lo split, swizzled.
// ---------------------------------------------------------------------------
#define PREP_SMEM (128 * 129 * 4)

__device__ __forceinline__ void split_store(unsigned char* img, uint32_t off,
                                            float v0, float v1, float v2,
                                            float v3) {
    __half h0 = __float2half_rn(v0), h1 = __float2half_rn(v1);
    __half h2 = __float2half_rn(v2), h3 = __float2half_rn(v3);
    __half l0 = __float2half_rn(v0 - __half2float(h0));
    __half l1 = __float2half_rn(v1 - __half2float(h1));
    __half l2 = __float2half_rn(v2 - __half2float(h2));
    __half l3 = __float2half_rn(v3 - __half2float(h3));
    uint32_t H01 = (uint32_t)__half_as_ushort(h0) |
                   ((uint32_t)__half_as_ushort(h1) << 16);
    uint32_t H23 = (uint32_t)__half_as_ushort(h2) |
                   ((uint32_t)__half_as_ushort(h3) << 16);
    uint32_t L01 = (uint32_t)__half_as_ushort(l0) |
                   ((uint32_t)__half_as_ushort(l1) << 16);
    uint32_t L23 = (uint32_t)__half_as_ushort(l2) |
                   ((uint32_t)__half_as_ushort(l3) << 16);
    *(uint2*)(img + off) = make_uint2(H01, H23);
    *(uint2*)(img + B_PART + off) = make_uint2(L01, L23);
}

__global__ void __launch_bounds__(256) prep_kernel(const float* __restrict__ M,
                                                   const float* __restrict__ z)
{
    extern __shared__ float ps[];
    const int h = blockIdx.x;
    const int tid = threadIdx.x;
    const float* Mh = M + (size_t)h * 16384;

    for (int i = tid; i < 4096; i += 256) {      // float4 over [k][n]
        int k = i >> 5, c4 = i & 31;
        float4 m = ((const float4*)Mh)[i];
        float* p = ps + k * 129 + c4 * 4;
        p[0] = m.x; p[1] = m.y; p[2] = m.z; p[3] = m.w;
    }
    __syncthreads();

    unsigned char* img = g_Bimg + (size_t)h * B_IMG;
    for (int i = tid; i < 4096; i += 256) {      // (n, kc4)
        int n = i >> 5, kc = i & 31;
        split_store(img, sw_off(n, kc),
                    ps[(kc * 4 + 0) * 129 + n], ps[(kc * 4 + 1) * 129 + n],
                    ps[(kc * 4 + 2) * 129 + n], ps[(kc * 4 + 3) * 129 + n]);
    }
    if (tid < 32) {                              // z row at n=128
        float4 zv = *(const float4*)(z + h * 128 + tid * 4);
        split_store(img, sw_off(128, tid), zv.x, zv.y, zv.z, zv.w);
    }
    if (tid < 224) {                             // zero rows 129..135
        *(uint64_t*)(img + 129 * 256 + tid * 8) = 0ULL;
        *(uint64_t*)(img + B_PART + 129 * 256 + tid * 8) = 0ULL;
    }
}

// ---------------------------------------------------------------------------
// fused kernel: blocks 0..255 retrieve, 256..511 update. 256 threads.
// ---------------------------------------------------------------------------
// retrieve smem layout
#define RT_SM_B 0
#define RT_SM_A 69632
#define RT_SM_STG 102400
#define RT_SM_NORM 167936
#define RT_TILES 8
// update smem layout
#define UP_AH 0
#define UP_BH 16384
#define UP_BL 32768
#define UP_STG 49152
#define FUSED_SMEM 180224

__device__ __forceinline__ void retrieve_part(unsigned char* sm, uint32_t sb,
                                              const float* __restrict__ Q,
                                              float* __restrict__ out,
                                              int bid)
{
    const int tid = threadIdx.x;
    const int l = tid & 31;
    const int wid = tid >> 5;
    const int wr = wid & 1;
    const int wc = wid >> 1;
    const int bh = bid >> 2;
    const int h = bh & 31;
    const int tbase = (bid & 3) * (RT_TILES * 128);

    const float* Qt = Q + ((size_t)bh * T_SZ + tbase) * D_SZ;
    float* ob = out + ((size_t)bh * T_SZ + tbase) * D_SZ;

    {
        const unsigned char* bimg = g_Bimg + (size_t)h * B_IMG;
        for (int i = tid; i < B_IMG / 16; i += 256)
            cpa16(sb + RT_SM_B + i * 16, bimg + (size_t)i * 16);
        for (int i = tid; i < 4096; i += 256)
            cpa16(sb + RT_SM_STG + i * 16, (const char*)Qt + (size_t)i * 16);
        CP_COMMIT();
    }

    const int arowl = l & 15;
    const int ag = (l >> 4) & 1;
    const int a7 = arowl & 7;
    const int browl = (l & 7) + ((l >> 4) << 3);
    const int bg = (l >> 3) & 1;
    const int b7 = browl & 7;
    const int le = l & 15;
    const int zrow = 128 + (le & 7);
    const int zg = (le >> 3) & 1;
    const int z7 = zrow & 7;

    uint32_t aoffm[4], boffp[2];
    #pragma unroll
    for (int mi = 0; mi < 4; ++mi)
        aoffm[mi] = (uint32_t)((wr * 64 + mi * 16 + arowl) * 256);
    #pragma unroll
    for (int p = 0; p < 2; ++p)
        boffp[p] = (uint32_t)((wc * 32 + p * 16 + browl) * 256);
    const uint32_t zoff = (uint32_t)(zrow * 256);

    for (int tile = 0; tile < RT_TILES; ++tile) {
        CP_WAIT0();
        __syncthreads();

        // convert stage (fp32) -> single-f16 A, swizzled
        #pragma unroll
        for (int i = 0; i < 16; ++i) {
            int idx = tid + i * 256;
            int row = idx >> 5, c4 = idx & 31;
            float4 q = *(const float4*)(sm + RT_SM_STG + (size_t)idx * 16);
            uint32_t h01 = pkh2(phi(q.x), phi(q.y));
            uint32_t h23 = pkh2(phi(q.z), phi(q.w));
            *(uint2*)(sm + RT_SM_A + sw_off(row, c4)) = make_uint2(h01, h23);
        }
        __syncthreads();

        if (tile + 1 < RT_TILES) {
            const char* nq = (const char*)(Qt + (size_t)(tile + 1) * 16384);
            for (int i = tid; i < 4096; i += 256)
                cpa16(sb + RT_SM_STG + i * 16, nq + (size_t)i * 16);
        }
        CP_COMMIT();

        float acc[4][4][4];
        float zac[4][4];
        #pragma unroll
        for (int mi = 0; mi < 4; ++mi) {
            #pragma unroll
            for (int nj = 0; nj < 4; ++nj)
                #pragma unroll
                for (int q = 0; q < 4; ++q) acc[mi][nj][q] = 0.f;
            #pragma unroll
            for (int q = 0; q < 4; ++q) zac[mi][q] = 0.f;
        }

        #pragma unroll
        for (int ks = 0; ks < 8; ++ks) {
            const int cb = ks * 2;
            const uint32_t ach = (uint32_t)((cb + ag) ^ a7) << 4;
            const uint32_t bch = (uint32_t)((cb + bg) ^ b7) << 4;

            uint32_t AF[4][4];
            #pragma unroll
            for (int mi = 0; mi < 4; ++mi)
                ldm4(AF[mi], sb + RT_SM_A + aoffm[mi] + ach);

            uint32_t BhF[4][2], BlF[4][2];
            #pragma unroll
            for (int p = 0; p < 2; ++p) {
                uint32_t r[4];
                ldm4(r, sb + RT_SM_B + boffp[p] + bch);
                BhF[2 * p][0] = r[0]; BhF[2 * p][1] = r[1];
                BhF[2 * p + 1][0] = r[2]; BhF[2 * p + 1][1] = r[3];
                ldm4(r, sb + RT_SM_B + B_PART + boffp[p] + bch);
                BlF[2 * p][0] = r[0]; BlF[2 * p][1] = r[1];
                BlF[2 * p + 1][0] = r[2]; BlF[2 * p + 1][1] = r[3];
            }

            #pragma unroll
            for (int mi = 0; mi < 4; ++mi)
                #pragma unroll
                for (int nj = 0; nj < 4; ++nj)
                    mma16816(acc[mi][nj], AF[mi], BhF[nj]);
            #pragma unroll
            for (int mi = 0; mi < 4; ++mi)
                #pragma unroll
                for (int nj = 0; nj < 4; ++nj)
                    mma16816(acc[mi][nj], AF[mi], BlF[nj]);

            if ((ks & 3) == wc) {
                const uint32_t zch = (uint32_t)((cb + zg) ^ z7) << 4;
                uint32_t zh[2], zl2[2];
                ldm2(zh, sb + RT_SM_B + zoff + zch);
                ldm2(zl2, sb + RT_SM_B + B_PART + zoff + zch);
                #pragma unroll
                for (int mi = 0; mi < 4; ++mi) {
                    mma16816(zac[mi], AF[mi], zh);
                    mma16816(zac[mi], AF[mi], zl2);
                }
            }
        }

        float* norms = (float*)(sm + RT_SM_NORM);   // [4][128]
        if ((l & 3) == 0) {
            #pragma unroll
            for (int mi = 0; mi < 4; ++mi) {
                int r = wr * 64 + mi * 16 + (l >> 2);
                norms[wc * 128 + r] = zac[mi][0];
                norms[wc * 128 + r + 8] = zac[mi][2];
            }
        }
        __syncthreads();

        #pragma unroll
        for (int mi = 0; mi < 4; ++mi) {
            int r = wr * 64 + mi * 16 + (l >> 2);
            float n1 = norms[r] + norms[128 + r] + norms[256 + r] + norms[384 + r];
            float n2 = norms[r + 8] + norms[128 + r + 8] + norms[256 + r + 8] +
                       norms[384 + r + 8];
            float i1 = 1.0f / fmaxf(n1, 1e-6f);
            float i2 = 1.0f / fmaxf(n2, 1e-6f);
            float* o1 = ob + (size_t)(tile * 128 + r) * 128 + wc * 32 + (l & 3) * 2;
            float* o2 = o1 + (size_t)8 * 128;
            #pragma unroll
            for (int nj = 0; nj < 4; ++nj) {
                *(float2*)(o1 + nj * 8) =
                    make_float2(acc[mi][nj][0] * i1, acc[mi][nj][1] * i1);
                *(float2*)(o2 + nj * 8) =
                    make_float2(acc[mi][nj][2] * i2, acc[mi][nj][3] * i2);
            }
        }
        __syncthreads();
    }
}

__device__ __forceinline__ void update_part(unsigned char* sm, uint32_t sb,
                                            const float* __restrict__ K,
                                            const float* __restrict__ V,
                                            int ubid)
{
    const int tid = threadIdx.x;
    const int l = tid & 31;
    const int wid = tid >> 5;
    const int wr = wid & 1;
    const int wc = wid >> 1;
    const int c = ubid & 7;
    const int h = ubid >> 3;

    const char* K0 = (const char*)(K + ((size_t)h * T_SZ + c * CHUNK_T) * D_SZ);
    const char* K1 = (const char*)(K + ((size_t)(H_SZ + h) * T_SZ + c * CHUNK_T) * D_SZ);
    const char* V0 = (const char*)(V + ((size_t)h * T_SZ + c * CHUNK_T) * D_SZ);
    const char* V1 = (const char*)(V + ((size_t)(H_SZ + h) * T_SZ + c * CHUNK_T) * D_SZ);

    for (int i = tid; i < 2048; i += 256) {
        cpa16(sb + UP_STG + i * 16, K0 + (size_t)i * 16);
        cpa16(sb + UP_STG + 32768 + i * 16, K1 + (size_t)i * 16);
        cpa16(sb + UP_STG + 65536 + i * 16, V0 + (size_t)i * 16);
        cpa16(sb + UP_STG + 98304 + i * 16, V1 + (size_t)i * 16);
    }
    CP_COMMIT();

    const int atr = (l & 7) + ((l >> 4) << 3);
    const int aag = (l >> 3) & 1;
    const int at7 = atr & 7;
    const int btr = (l & 7) + (((l >> 3) & 1) << 3);
    const int bbg = (l >> 4) & 1;
    const int bt7 = btr & 7;

    float acc[4][4][4];
    #pragma unroll
    for (int mi = 0; mi < 4; ++mi)
        #pragma unroll
        for (int nj = 0; nj < 4; ++nj)
            #pragma unroll
            for (int q = 0; q < 4; ++q) acc[mi][nj][q] = 0.f;
    float za0 = 0.f, za1 = 0.f, za2 = 0.f, za3 = 0.f;
    const int myc4 = tid & 31;

    for (int si = 0; si < 8; ++si) {
        CP_WAIT0();
        __syncthreads();

        #pragma unroll
        for (int i = 0; i < 8; ++i) {
            int idx = tid + i * 256;
            int row = idx >> 5;
            float4 k0 = *(const float4*)(sm + UP_STG + (size_t)idx * 16);
            float4 k1 = *(const float4*)(sm + UP_STG + 32768 + (size_t)idx * 16);
            float a0 = 0.5f * (phi(k0.x) + phi(k1.x));
            float a1 = 0.5f * (phi(k0.y) + phi(k1.y));
            float a2 = 0.5f * (phi(k0.z) + phi(k1.z));
            float a3 = 0.5f * (phi(k0.w) + phi(k1.w));
            za0 += a0; za1 += a1; za2 += a2; za3 += a3;
            uint32_t off = sw_off(row, myc4);
            *(uint2*)(sm + UP_AH + off) =
                make_uint2(pkh2(a0, a1), pkh2(a2, a3));

            float4 v0 = *(const float4*)(sm + UP_STG + 65536 + (size_t)idx * 16);
            float4 v1 = *(const float4*)(sm + UP_STG + 98304 + (size_t)idx * 16);
            float b0 = 0.5f * (v0.x + v1.x), b1 = 0.5f * (v0.y + v1.y);
            float b2 = 0.5f * (v0.z + v1.z), b3 = 0.5f * (v0.w + v1.w);
            __half hb0 = __float2half_rn(b0), hb1 = __float2half_rn(b1);
            __half hb2 = __float2half_rn(b2), hb3 = __float2half_rn(b3);
            uint32_t bh01 = (uint32_t)__half_as_ushort(hb0) |
                            ((uint32_t)__half_as_ushort(hb1) << 16);
            uint32_t bh23 = (uint32_t)__half_as_ushort(hb2) |
                            ((uint32_t)__half_as_ushort(hb3) << 16);
            uint32_t bl01 = pkh2(b0 - __half2float(hb0), b1 - __half2float(hb1));
            uint32_t bl23 = pkh2(b2 - __half2float(hb2), b3 - __half2float(hb3));
            *(uint2*)(sm + UP_BH + off) = make_uint2(bh01, bh23);
            *(uint2*)(sm + UP_BL + off) = make_uint2(bl01, bl23);
        }
        __syncthreads();

        if (si + 1 < 8) {
            size_t go = (size_t)(si + 1) * 32768;
            for (int i = tid; i < 2048; i += 256) {
                cpa16(sb + UP_STG + i * 16, K0 + go + (size_t)i * 16);
                cpa16(sb + UP_STG + 32768 + i * 16, K1 + go + (size_t)i * 16);
                cpa16(sb + UP_STG + 65536 + i * 16, V0 + go + (size_t)i * 16);
                cpa16(sb + UP_STG + 98304 + i * 16, V1 + go + (size_t)i * 16);
            }
        }
        CP_COMMIT();

        #pragma unroll
        for (int ks = 0; ks < 4; ++ks) {
            const int k0t = ks * 16;
            uint32_t AF[4][4];
            #pragma unroll
            for (int mi = 0; mi < 4; ++mi) {
                uint32_t ch = (uint32_t)(((wr * 8 + mi * 2 + aag) ^ at7) << 4);
                ldm4t(AF[mi], sb + UP_AH + (uint32_t)((k0t + atr) * 256) + ch);
            }
            uint32_t BhF[4][2], BlF[4][2];
            #pragma unroll
            for (int p = 0; p < 2; ++p) {
                uint32_t ch = (uint32_t)(((wc * 4 + p * 2 + bbg) ^ bt7) << 4);
                uint32_t addr = (uint32_t)((k0t + btr) * 256) + ch;
                uint32_t r[4];
                ldm4t(r, sb + UP_BH + addr);
                BhF[2 * p][0] = r[0]; BhF[2 * p][1] = r[1];
                BhF[2 * p + 1][0] = r[2]; BhF[2 * p + 1][1] = r[3];
                ldm4t(r, sb + UP_BL + addr);
                BlF[2 * p][0] = r[0]; BlF[2 * p][1] = r[1];
                BlF[2 * p + 1][0] = r[2]; BlF[2 * p + 1][1] = r[3];
            }
            #pragma unroll
            for (int mi = 0; mi < 4; ++mi)
                #pragma unroll
                for (int nj = 0; nj < 4; ++nj)
                    mma16816(acc[mi][nj], AF[mi], BhF[nj]);
            #pragma unroll
            for (int mi = 0; mi < 4; ++mi)
                #pragma unroll
                for (int nj = 0; nj < 4; ++nj)
                    mma16816(acc[mi][nj], AF[mi], BlF[nj]);
        }
    }
    __syncthreads();

    float* zr = (float*)(sm + UP_STG);              // [8][128]
    *(float4*)(zr + (tid >> 5) * 128 + myc4 * 4) = make_float4(za0, za1, za2, za3);
    __syncthreads();
    if (tid < 128) {
        float s = 0.f;
        #pragma unroll
        for (int j = 0; j < 8; ++j) s += zr[j * 128 + tid];
        g_partZ[(h * NCHUNK + c) * 128 + tid] = s;
    }

    float* pm = g_partM + ((size_t)(h * NCHUNK + c) << 14);
    #pragma unroll
    for (int mi = 0; mi < 4; ++mi) {
        int r = wr * 64 + mi * 16 + (l >> 2);
        #pragma unroll
        for (int nj = 0; nj < 4; ++nj) {
            int col = wc * 32 + nj * 8 + (l & 3) * 2;
            *(float2*)(pm + (size_t)r * 128 + col) =
                make_float2(acc[mi][nj][0], acc[mi][nj][1]);
            *(float2*)(pm + (size_t)(r + 8) * 128 + col) =
                make_float2(acc[mi][nj][2], acc[mi][nj][3]);
        }
    }
}

__global__ void __launch_bounds__(256)
fused_hmma(const float* __restrict__ Q, const float* __restrict__ K,
           const float* __restrict__ V, float* __restrict__ out)
{
    extern __shared__ unsigned char sm[];
    const uint32_t sb = smem_u32(sm);
    const int bid = blockIdx.x;
    if (bid < 256) {
        retrieve_part(sm, sb, Q, out, bid);
    } else {
        update_part(sm, sb, K, V, bid - 256);
    }
}

// ---------------------------------------------------------------------------
// fixed-order reduction of partials + M/z add
// ---------------------------------------------------------------------------
__global__ void reduce_kernel(const float* __restrict__ M,
                              const float* __restrict__ z,
                              float* __restrict__ outM,
                              float* __restrict__ outZ)
{
    int idx = blockIdx.x * 256 + threadIdx.x;
    if (idx < MNEW_ELEMS) {
        int h = idx >> 14;
        int r = idx & 16383;
        float s = M[idx];
        #pragma unroll
        for (int cc = 0; cc < NCHUNK; ++cc)
            s += g_partM[((size_t)(h * NCHUNK + cc) << 14) + r];
        outM[idx] = s;
    } else {
        int j = idx - MNEW_ELEMS;
        if (j < ZNEW_ELEMS) {
            int h = j >> 7;
            int d = j & 127;
            float s = z[j];
            #pragma unroll
            for (int cc = 0; cc < NCHUNK; ++cc)
                s += g_partZ[(h * NCHUNK + cc) * 128 + d];
            outZ[j] = s;
        }
    }
}

// ---------------------------------------------------------------------------
extern "C" void kernel_launch(void* const* d_in, const int* in_sizes, int n_in,
                              void* d_out, int out_size)
{
    const float* Q = (const float*)d_in[0];
    const float* K = (const float*)d_in[1];
    const float* V = (const float*)d_in[2];
    const float* M = (const float*)d_in[3];
    const float* z = (const float*)d_in[4];

    float* out  = (float*)d_out;
    float* outM = out + OUT_ELEMS;
    float* outZ = outM + MNEW_ELEMS;

    cudaFuncSetAttribute(prep_kernel,
                         cudaFuncAttributeMaxDynamicSharedMemorySize, PREP_SMEM);
    cudaFuncSetAttribute(fused_hmma,
                         cudaFuncAttributeMaxDynamicSharedMemorySize, FUSED_SMEM);

    prep_kernel<<<H_SZ, 256, PREP_SMEM>>>(M, z);
    fused_hmma<<<512, 256, FUSED_SMEM>>>(Q, K, V, out);
    int red_threads = MNEW_ELEMS + ZNEW_ELEMS;
    reduce_kernel<<<(red_threads + 255) / 256, 256>>>(M, z, outM, outZ);
}